// round 1
// baseline (speedup 1.0000x reference)
#include <cuda_runtime.h>

#define GYc 1024
#define GXc 1024
#define NBEV 8
#define Pc 32
#define CIN 10
#define COUT 64
#define MAXN 40000
#define MAXB 2

// Scratch (no allocations allowed): owner grid for last-write-wins scatter,
// per-voxel BEV stats.
__device__ int   g_owner[MAXB * GYc * GXc];
__device__ float g_pbev[MAXN * NBEV];

// ---------------- warp reductions ----------------
__device__ __forceinline__ float wsum(float v) {
#pragma unroll
    for (int o = 16; o; o >>= 1) v += __shfl_xor_sync(0xffffffffu, v, o);
    return v;
}
__device__ __forceinline__ float wmax(float v) {
#pragma unroll
    for (int o = 16; o; o >>= 1) v = fmaxf(v, __shfl_xor_sync(0xffffffffu, v, o));
    return v;
}
__device__ __forceinline__ float wmin(float v) {
#pragma unroll
    for (int o = 16; o; o >>= 1) v = fminf(v, __shfl_xor_sync(0xffffffffu, v, o));
    return v;
}

// ---------------- packed f32x2 helpers (FFMA2; sm_100+) ----------------
__device__ __forceinline__ unsigned long long pk2(float lo, float hi) {
    unsigned long long r;
    asm("mov.b64 %0, {%1, %2};" : "=l"(r) : "f"(lo), "f"(hi));
    return r;
}
__device__ __forceinline__ void upk2(unsigned long long v, float& lo, float& hi) {
    asm("mov.b64 {%0, %1}, %2;" : "=f"(lo), "=f"(hi) : "l"(v));
}
__device__ __forceinline__ unsigned long long ffma2(unsigned long long a,
                                                    unsigned long long b,
                                                    unsigned long long c) {
    unsigned long long d;
    asm("fma.rn.f32x2 %0, %1, %2, %3;" : "=l"(d) : "l"(a), "l"(b), "l"(c));
    return d;
}

// ---------------- kernel 1: zero vox_bev + init owner ----------------
__global__ void k_zero(float4* __restrict__ bev4, int nbev4, int nown4) {
    int4* own4 = reinterpret_cast<int4*>(g_owner);
    int stride = gridDim.x * blockDim.x;
    int i = blockIdx.x * blockDim.x + threadIdx.x;
    float4 z = make_float4(0.f, 0.f, 0.f, 0.f);
    int4 m = make_int4(-1, -1, -1, -1);
    for (int j = i; j < nbev4; j += stride) bev4[j] = z;
    for (int j = i; j < nown4; j += stride) own4[j] = m;
}

// ---------------- kernel 2: per-voxel VFE (one warp per voxel) ----------------
__global__ __launch_bounds__(256) void k_main(
    const float4* __restrict__ vf,      // [N*P] float4 (x,y,z,intensity)
    const float*  __restrict__ Wm,      // [10][64]
    const float*  __restrict__ gamma,
    const float*  __restrict__ beta,
    const float*  __restrict__ rmean,
    const float*  __restrict__ rvar,
    const int*    __restrict__ vnp,     // [N]
    const int4*   __restrict__ coords,  // [N] (b,z,y,x)
    int N, int batch,
    float* __restrict__ out_pf)         // [N][64]
{
    __shared__ float sW[CIN][COUT];
    __shared__ __align__(16) float sF[8][CIN][Pc];  // transposed features, per warp

    int tid = threadIdx.x;
    for (int i = tid; i < CIN * COUT; i += 256) ((float*)sW)[i] = Wm[i];
    __syncthreads();

    int warp = tid >> 5, lane = tid & 31;
    int vid = blockIdx.x * 8 + warp;
    if (vid >= N) return;

    float4 pt = vf[(size_t)vid * Pc + lane];
    int   np    = vnp[vid];
    float npf   = (float)np;
    float inv_n = 1.0f / npf;
    bool  valid = lane < np;
    int4  cc    = coords[vid];

    // points_mean: sum over ALL P points / npts (reference does NOT mask here)
    float mxa = wsum(pt.x) * inv_n;
    float mya = wsum(pt.y) * inv_n;
    float mza = wsum(pt.z) * inv_n;

    // masked statistics for pillar_bev
    float px = valid ? pt.x : 0.f;
    float py = valid ? pt.y : 0.f;
    float pz = valid ? pt.z : 0.f;
    float pi = valid ? pt.w : 0.f;
    float pmx  = wsum(px) * inv_n;
    float pmy  = wsum(py) * inv_n;
    float pmz  = wsum(pz) * inv_n;       // mean_height
    float mint = wsum(pi) * inv_n;       // mean_intensity
    float zmax = wmax(valid ? pt.z : -1e6f);
    float zmin = wmin(valid ? pt.z :  1e6f);
    float dx = pt.x - pmx, dy = pt.y - pmy, dz = pt.z - pmz;
    float vvx = wsum(valid ? dx * dx : 0.f) * inv_n;
    float vvy = wsum(valid ? dy * dy : 0.f) * inv_n;
    float vvz = wsum(valid ? dz * dz : 0.f) * inv_n;

    // 10 augmented features for this lane's point (masked)
    float cx = (float)cc.w * 0.1f + (0.05f - 51.2f);
    float cy = (float)cc.z * 0.1f + (0.05f - 51.2f);
    float cz = (float)cc.y * 4.0f + (2.0f - 3.0f);
    float f[10];
    f[0] = px; f[1] = py; f[2] = pz; f[3] = pi;
    f[4] = valid ? pt.x - mxa : 0.f;
    f[5] = valid ? pt.y - mya : 0.f;
    f[6] = valid ? pt.z - mza : 0.f;
    f[7] = valid ? pt.x - cx  : 0.f;
    f[8] = valid ? pt.y - cy  : 0.f;
    f[9] = valid ? pt.z - cz  : 0.f;
#pragma unroll
    for (int c = 0; c < 10; c++) sF[warp][c][lane] = f[c];
    __syncwarp();

    // GEMM + BN + ReLU + max over points.
    // Lane owns output channels d0=lane, d1=lane+32.
    // Points processed in pairs via packed fma.rn.f32x2 (halves FMA instr count).
    unsigned long long w0d[10], w1d[10];
#pragma unroll
    for (int c = 0; c < 10; c++) {
        float a = sW[c][lane], b = sW[c][lane + 32];
        w0d[c] = pk2(a, a);
        w1d[c] = pk2(b, b);
    }
    float s0 = gamma[lane]      * rsqrtf(rvar[lane]      + 1e-3f);
    float b0 = beta[lane]       - rmean[lane]      * s0;
    float s1 = gamma[lane + 32] * rsqrtf(rvar[lane + 32] + 1e-3f);
    float b1 = beta[lane + 32]  - rmean[lane + 32] * s1;
    unsigned long long s0d = pk2(s0, s0), b0d = pk2(b0, b0);
    unsigned long long s1d = pk2(s1, s1), b1d = pk2(b1, b1);

    float m0 = 0.f, m1 = 0.f;  // relu output >= 0, nonempty set -> init 0 is exact
    const float2* fw = reinterpret_cast<const float2*>(&sF[warp][0][0]);  // [10][16]
#pragma unroll
    for (int pp = 0; pp < Pc / 2; pp++) {
        unsigned long long a0 = 0ull, a1 = 0ull;  // packed (0.f, 0.f)
#pragma unroll
        for (int c = 0; c < 10; c++) {
            float2 fv = fw[c * (Pc / 2) + pp];    // LDS.64 broadcast
            unsigned long long fp = pk2(fv.x, fv.y);
            a0 = ffma2(fp, w0d[c], a0);
            a1 = ffma2(fp, w1d[c], a1);
        }
        a0 = ffma2(a0, s0d, b0d);                 // fused BN
        a1 = ffma2(a1, s1d, b1d);
        float u, v;
        upk2(a0, u, v);
        m0 = fmaxf(m0, fmaxf(u, v));              // max(...,0 init) == relu-of-max
        upk2(a1, u, v);
        m1 = fmaxf(m1, fmaxf(u, v));
    }

    out_pf[(size_t)vid * COUT + lane]      = m0;
    out_pf[(size_t)vid * COUT + lane + 32] = m1;

    if (lane == 0) {
        float pb[8] = { npf * (1.f / 32.f), mint, pmz, zmax,
                        zmax - zmin, vvx, vvy, vvz };
#pragma unroll
        for (int c = 0; c < 8; c++) g_pbev[vid * 8 + c] = pb[c];
        int b = min(max(cc.x, 0), batch - 1);
        int cell = (b * GYc + cc.z) * GXc + cc.w;
        atomicMax(&g_owner[cell], vid);   // last-index-wins like sequential scatter
    }
}

// ---------------- kernel 3: owner-checked BEV scatter ----------------
__global__ void k_scatter(const int4* __restrict__ coords, int N, int batch,
                          float* __restrict__ bev) {
    int vid = blockIdx.x * blockDim.x + threadIdx.x;
    if (vid >= N) return;
    int4 cc = coords[vid];
    int b = min(max(cc.x, 0), batch - 1);
    int cell = (b * GYc + cc.z) * GXc + cc.w;
    if (g_owner[cell] != vid) return;
    size_t base = ((size_t)(b * NBEV) * GYc + cc.z) * GXc + cc.w;
#pragma unroll
    for (int c = 0; c < 8; c++)
        bev[base + (size_t)c * GYc * GXc] = g_pbev[vid * 8 + c];
}

extern "C" void kernel_launch(void* const* d_in, const int* in_sizes, int n_in,
                              void* d_out, int out_size) {
    const float* vf     = (const float*)d_in[0];
    const float* Wm     = (const float*)d_in[1];
    const float* gam    = (const float*)d_in[2];
    const float* bet    = (const float*)d_in[3];
    const float* rmean  = (const float*)d_in[4];
    const float* rvar   = (const float*)d_in[5];
    const int*   vnp    = (const int*)d_in[6];
    const int*   coords = (const int*)d_in[7];
    int N     = in_sizes[6];
    int batch = in_sizes[8];

    float* out_pf = (float*)d_out;                       // [N,64]
    float* bev    = out_pf + (size_t)N * COUT;           // [batch,8,1024,1024]

    int nbev = batch * NBEV * GYc * GXc;
    int nown = batch * GYc * GXc;

    k_zero<<<2048, 256>>>(reinterpret_cast<float4*>(bev), nbev / 4, nown / 4);
    k_main<<<(N + 7) / 8, 256>>>(reinterpret_cast<const float4*>(vf), Wm,
                                 gam, bet, rmean, rvar, vnp,
                                 reinterpret_cast<const int4*>(coords),
                                 N, batch, out_pf);
    k_scatter<<<(N + 255) / 256, 256>>>(reinterpret_cast<const int4*>(coords),
                                        N, batch, bev);
}

// round 3
// speedup vs baseline: 1.1317x; 1.1317x over previous
#include <cuda_runtime.h>

#define GYc 1024
#define GXc 1024
#define NBEV 8
#define Pc 32
#define CIN 10
#define COUT 64
#define MAXN 40000
#define MAXB 2

__device__ int   g_owner[MAXB * GYc * GXc];
__device__ float g_pbev[MAXN * NBEV];

// ---------------- warp reductions ----------------
__device__ __forceinline__ float wsum(float v) {
#pragma unroll
    for (int o = 16; o; o >>= 1) v += __shfl_xor_sync(0xffffffffu, v, o);
    return v;
}
__device__ __forceinline__ float wmax(float v) {
#pragma unroll
    for (int o = 16; o; o >>= 1) v = fmaxf(v, __shfl_xor_sync(0xffffffffu, v, o));
    return v;
}
__device__ __forceinline__ float wmin(float v) {
#pragma unroll
    for (int o = 16; o; o >>= 1) v = fminf(v, __shfl_xor_sync(0xffffffffu, v, o));
    return v;
}

// ---------------- packed f32x2 helpers (sm_100+) ----------------
__device__ __forceinline__ unsigned long long pk2(float lo, float hi) {
    unsigned long long r;
    asm("mov.b64 %0, {%1, %2};" : "=l"(r) : "f"(lo), "f"(hi));
    return r;
}
__device__ __forceinline__ void upk2(unsigned long long v, float& lo, float& hi) {
    asm("mov.b64 {%0, %1}, %2;" : "=f"(lo), "=f"(hi) : "l"(v));
}
__device__ __forceinline__ unsigned long long ffma2(unsigned long long a,
                                                    unsigned long long b,
                                                    unsigned long long c) {
    unsigned long long d;
    asm("fma.rn.f32x2 %0, %1, %2, %3;" : "=l"(d) : "l"(a), "l"(b), "l"(c));
    return d;
}

// ---------------- kernel 0: owner init (must precede atomicMax) ----------------
__global__ void k_own(int nown4) {
    int4* own4 = reinterpret_cast<int4*>(g_owner);
    int stride = gridDim.x * blockDim.x;
    int4 m = make_int4(-1, -1, -1, -1);
    for (int j = blockIdx.x * blockDim.x + threadIdx.x; j < nown4; j += stride)
        own4[j] = m;
}

// ---------------- kernel 1: fused voxel VFE + bev zero ----------------
// Blocks [0, VB): one warp per voxel (8 voxels/block).
// Blocks [VB, VB+ZB): grid-stride zero of vox_bev ONLY (safe: only the
// scatter kernel, launched after, reads/writes bev).
__global__ __launch_bounds__(256) void k_fused(
    const float4* __restrict__ vf,      // [N*P] (x,y,z,intensity)
    const float*  __restrict__ Wm,      // [10][64]
    const float*  __restrict__ gamma,
    const float*  __restrict__ beta,
    const float*  __restrict__ rmean,
    const float*  __restrict__ rvar,
    const int*    __restrict__ vnp,     // [N]
    const int4*   __restrict__ coords,  // [N] (b,z,y,x)
    int N, int batch, int VB, int ZB,
    float* __restrict__ out_pf,         // [N][64]
    float4* __restrict__ bev4, int nbev4)
{
    if (blockIdx.x >= VB) {
        int stride = ZB * 256;
        float4 z = make_float4(0.f, 0.f, 0.f, 0.f);
        for (int j = (blockIdx.x - VB) * 256 + threadIdx.x; j < nbev4; j += stride)
            bev4[j] = z;
        return;
    }

    // ---------- voxel path ----------
    __shared__ float sW[CIN][COUT];
    __shared__ __align__(16) float sF[8][CIN][Pc];

    int tid = threadIdx.x;
    for (int i = tid; i < CIN * COUT; i += 256) ((float*)sW)[i] = Wm[i];
    __syncthreads();

    int warp = tid >> 5, lane = tid & 31;
    int vid = blockIdx.x * 8 + warp;
    if (vid >= N) return;

    float4 pt = vf[(size_t)vid * Pc + lane];
    int   np    = vnp[vid];
    float npf   = (float)np;
    float inv_n = 1.0f / npf;
    bool  valid = lane < np;
    int4  cc    = coords[vid];

    float px = valid ? pt.x : 0.f;
    float py = valid ? pt.y : 0.f;
    float pz = valid ? pt.z : 0.f;
    float pi = valid ? pt.w : 0.f;

    // independent warp reductions (variance via E[p^2]-m^2)
    float sxa = wsum(pt.x);             // unmasked (reference points_mean)
    float sya = wsum(pt.y);
    float sza = wsum(pt.z);
    float sx  = wsum(px);
    float sy  = wsum(py);
    float sz  = wsum(pz);
    float si  = wsum(pi);
    float sxx = wsum(px * px);
    float syy = wsum(py * py);
    float szz = wsum(pz * pz);
    float zmax = wmax(valid ? pt.z : -1e6f);
    float zmin = wmin(valid ? pt.z :  1e6f);

    float mxa = sxa * inv_n, mya = sya * inv_n, mza = sza * inv_n;
    float pmx = sx * inv_n, pmy = sy * inv_n, pmz = sz * inv_n;
    float mint = si * inv_n;
    float vvx = fmaxf(sxx * inv_n - pmx * pmx, 0.f);
    float vvy = fmaxf(syy * inv_n - pmy * pmy, 0.f);
    float vvz = fmaxf(szz * inv_n - pmz * pmz, 0.f);

    // 10 augmented features (masked)
    float cx = (float)cc.w * 0.1f + (0.05f - 51.2f);
    float cy = (float)cc.z * 0.1f + (0.05f - 51.2f);
    float cz = (float)cc.y * 4.0f + (2.0f - 3.0f);
    float f[10];
    f[0] = px; f[1] = py; f[2] = pz; f[3] = pi;
    f[4] = valid ? pt.x - mxa : 0.f;
    f[5] = valid ? pt.y - mya : 0.f;
    f[6] = valid ? pt.z - mza : 0.f;
    f[7] = valid ? pt.x - cx  : 0.f;
    f[8] = valid ? pt.y - cy  : 0.f;
    f[9] = valid ? pt.z - cz  : 0.f;
#pragma unroll
    for (int c = 0; c < 10; c++) sF[warp][c][lane] = f[c];
    __syncwarp();

    // BN folded into weights: x_d = sum_c f_c * (W[c][d]*s_d) + b_d
    float s0 = gamma[lane]      * rsqrtf(rvar[lane]      + 1e-3f);
    float b0 = beta[lane]       - rmean[lane]      * s0;
    float s1 = gamma[lane + 32] * rsqrtf(rvar[lane + 32] + 1e-3f);
    float b1 = beta[lane + 32]  - rmean[lane + 32] * s1;

    unsigned long long w0d[10], w1d[10];
#pragma unroll
    for (int c = 0; c < 10; c++) {
        float a = sW[c][lane] * s0, b = sW[c][lane + 32] * s1;
        w0d[c] = pk2(a, a);
        w1d[c] = pk2(b, b);
    }
    unsigned long long b0d = pk2(b0, b0), b1d = pk2(b1, b1);

    // Masked points contribute exactly b_d; account for them once, then loop
    // only over valid point-pairs (an odd-np trailing zero point in the last
    // pair evaluates to b_d too -> consistent).
    float m0 = (np < Pc) ? b0 : -3e38f;
    float m1 = (np < Pc) ? b1 : -3e38f;

    int npp = (np + 1) >> 1;  // warp-uniform
    const float2* fw = reinterpret_cast<const float2*>(&sF[warp][0][0]);  // [10][16]
#pragma unroll 4
    for (int pp = 0; pp < npp; pp++) {
        unsigned long long a0 = b0d, a1 = b1d;
#pragma unroll
        for (int c = 0; c < 10; c++) {
            float2 fv = fw[c * (Pc / 2) + pp];    // LDS.64 broadcast
            unsigned long long fp = pk2(fv.x, fv.y);
            a0 = ffma2(fp, w0d[c], a0);
            a1 = ffma2(fp, w1d[c], a1);
        }
        float u, v;
        upk2(a0, u, v);
        m0 = fmaxf(m0, fmaxf(u, v));
        upk2(a1, u, v);
        m1 = fmaxf(m1, fmaxf(u, v));
    }

    out_pf[(size_t)vid * COUT + lane]      = fmaxf(m0, 0.f);  // relu(max)=max(relu)
    out_pf[(size_t)vid * COUT + lane + 32] = fmaxf(m1, 0.f);

    if (lane == 0) {
        float pb[8] = { npf * (1.f / 32.f), mint, pmz, zmax,
                        zmax - zmin, vvx, vvy, vvz };
#pragma unroll
        for (int c = 0; c < 8; c++) g_pbev[vid * 8 + c] = pb[c];
        int b = min(max(cc.x, 0), batch - 1);
        int cell = (b * GYc + cc.z) * GXc + cc.w;
        atomicMax(&g_owner[cell], vid);   // last-index-wins (owner pre-set to -1)
    }
}

// ---------------- kernel 2: owner-checked BEV scatter ----------------
__global__ void k_scatter(const int4* __restrict__ coords, int N, int batch,
                          float* __restrict__ bev) {
    int vid = blockIdx.x * blockDim.x + threadIdx.x;
    if (vid >= N) return;
    int4 cc = coords[vid];
    int b = min(max(cc.x, 0), batch - 1);
    int cell = (b * GYc + cc.z) * GXc + cc.w;
    if (g_owner[cell] != vid) return;
    size_t base = ((size_t)(b * NBEV) * GYc + cc.z) * GXc + cc.w;
#pragma unroll
    for (int c = 0; c < 8; c++)
        bev[base + (size_t)c * GYc * GXc] = g_pbev[vid * 8 + c];
}

extern "C" void kernel_launch(void* const* d_in, const int* in_sizes, int n_in,
                              void* d_out, int out_size) {
    const float* vf     = (const float*)d_in[0];
    const float* Wm     = (const float*)d_in[1];
    const float* gam    = (const float*)d_in[2];
    const float* bet    = (const float*)d_in[3];
    const float* rmean  = (const float*)d_in[4];
    const float* rvar   = (const float*)d_in[5];
    const int*   vnp    = (const int*)d_in[6];
    const int*   coords = (const int*)d_in[7];
    int N     = in_sizes[6];
    int batch = in_sizes[8];

    float* out_pf = (float*)d_out;                       // [N,64]
    float* bev    = out_pf + (size_t)N * COUT;           // [batch,8,1024,1024]

    int nbev = batch * NBEV * GYc * GXc;
    int nown = batch * GYc * GXc;
    int VB = (N + 7) / 8;
    int ZB = 1024;

    k_own<<<512, 256>>>(nown / 4);
    k_fused<<<VB + ZB, 256>>>(reinterpret_cast<const float4*>(vf), Wm,
                              gam, bet, rmean, rvar, vnp,
                              reinterpret_cast<const int4*>(coords),
                              N, batch, VB, ZB, out_pf,
                              reinterpret_cast<float4*>(bev), nbev / 4);
    k_scatter<<<(N + 255) / 256, 256>>>(reinterpret_cast<const int4*>(coords),
                                        N, batch, bev);
}